// round 15
// baseline (speedup 1.0000x reference)
#include <cuda_runtime.h>
#include <cuda_fp16.h>
#include <cstdint>
#include <math.h>

// Problem constants
#define BB   4
#define TT   4
#define CC   32
#define NN   16384
#define FF   64
#define KK   9
#define PADD 4

// Tiling
#define NT    256               // n per block
#define XS    (NT + 2*PADD)     // 264 (u32 row stride of packed x; 264%32=8 -> conflict-free)
#define KDIM  (CC * KK)         // 288 = GEMM K
#define NTHREADS 256

// SMEM layout (bytes)
// s_wb2: fragment-ordered W. uint2 per (k,h,ft,lane): .x = f16x2 B-word for k8-lo, .y for k8-hi
#define SWB2_U2    (KK * 2 * 8 * 32)         // 4608 uint2 = 36864 B
#define SX2_WORDS  (16 * XS)                 // 4224 u32  = 16896 B (f16x2 x pairs along c)
#define SC_ELEMS   (3 * XS)                  // 792 f32   = 3168 B
#define SDW_ELEMS  (KK * NT)                 // 2304 f32  = 9216 B
#define SMEM_BYTES (SWB2_U2*8 + SX2_WORDS*4 + SC_ELEMS*4 + SDW_ELEMS*4)   // 66144

__device__ __forceinline__ unsigned pack_f16x2(float lo, float hi) {
    unsigned r;
    asm("cvt.rn.f16x2.f32 %0, %1, %2;" : "=r"(r) : "f"(hi), "f"(lo));
    return r;
}

// t = A*B + C  (separate C regs; used with zeros for first step)
#define MMA_F16_INIT(t, a0, a1, a2, a3, b0, b1, z)                             \
    asm volatile("mma.sync.aligned.m16n8k16.row.col.f32.f16.f16.f32 "          \
                 "{%0,%1,%2,%3}, {%4,%5,%6,%7}, {%8,%9}, {%10,%10,%10,%10};"   \
                 : "=f"(t[0]), "=f"(t[1]), "=f"(t[2]), "=f"(t[3])              \
                 : "r"(a0), "r"(a1), "r"(a2), "r"(a3), "r"(b0), "r"(b1), "f"(z))

#define MMA_F16_ACC(t, a0, a1, a2, a3, b0, b1)                                 \
    asm volatile("mma.sync.aligned.m16n8k16.row.col.f32.f16.f16.f32 "          \
                 "{%0,%1,%2,%3}, {%4,%5,%6,%7}, {%8,%9}, {%0,%1,%2,%3};"       \
                 : "+f"(t[0]), "+f"(t[1]), "+f"(t[2]), "+f"(t[3])              \
                 : "r"(a0), "r"(a1), "r"(a2), "r"(a3), "r"(b0), "r"(b1))

__device__ __forceinline__ float decode_sigma(const void* p) {
    const unsigned* w = (const unsigned*)p;
    unsigned lo = w[0];
    if (lo >= 1u && lo <= 1000000u) return (float)lo;          // int32/int64 low word
    float f = __uint_as_float(lo);
    if (f > 1e-6f && f < 1e6f) return f;                        // float32
    return (float)(*(const double*)p);                          // float64
}

__global__ __launch_bounds__(NTHREADS, 2)
void swconv1d_mma16b_kernel(const float* __restrict__ x,
                            const float* __restrict__ coords,
                            const float* __restrict__ weight,
                            const void*  __restrict__ sig,
                            float* __restrict__ out)
{
    extern __shared__ char smem_raw[];
    uint2*    s_wb2 = (uint2*)smem_raw;                          // [18*8][32] uint2
    unsigned* s_x2  = (unsigned*)(smem_raw + SWB2_U2 * 8);       // [16][XS] f16x2 (c pairs)
    float*    s_c   = (float*)(smem_raw + SWB2_U2*8 + SX2_WORDS*4);
    float*    s_dw  = s_c + SC_ELEMS;                            // [K][NT] f32

    const int tid    = threadIdx.x;
    const int wid    = tid >> 5;                 // 0..7
    const int lane   = tid & 31;
    const int gid    = lane >> 2;                // groupID (0..7)
    const int tig    = lane & 3;                 // threadID_in_group (0..3)
    const int bt     = blockIdx.y;
    const int t      = bt & 3;
    const int n_base = blockIdx.x * NT;

    const float inv_sigma = 1.0f / decode_sigma(sig);

    // ---- stage W[t] fragment-ordered: uint2 per (k, h, ft, lane) ----
    // lane' = gid'*4 + tig'; qp = k*16 + h*8 + tig'; f = ft*8 + gid'
    // .x = f16x2(W[f][c=16h+2tig'][k], W[f][c+1][k]); .y = same at c+8
    {
        const float* wt = weight + (size_t)t * FF * KDIM;
        for (int i = tid; i < SWB2_U2; i += NTHREADS) {
            int lp  = i & 31;
            int ft  = (i >> 5) & 7;
            int s   = i >> 8;                    // 0..17
            int k   = s >> 1;
            int h   = s & 1;
            int gg  = lp >> 2;
            int tg  = lp & 3;
            int f   = ft * 8 + gg;
            int cl  = h * 16 + 2 * tg;
            const float* wf = wt + (size_t)f * KDIM + k;   // wt[f*288 + c*9 + k]
            uint2 u;
            u.x = pack_f16x2(wf[(size_t)cl * KK],       wf[(size_t)(cl + 1) * KK]);
            u.y = pack_f16x2(wf[(size_t)(cl + 8) * KK], wf[(size_t)(cl + 9) * KK]);
            s_wb2[i] = u;
        }
    }
    // ---- stage x as f16x2 c-pairs: s_x2[c2][m] = (x[2c2][n], x[2c2+1][n]) ----
    {
        const float* xb = x + (size_t)bt * CC * NN;
        for (int i = tid; i < SX2_WORDS; i += NTHREADS) {
            int c2 = i / XS;
            int m  = i - c2 * XS;
            int n  = n_base + m - PADD;
            float lo = 0.0f, hi = 0.0f;
            if (n >= 0 && n < NN) {
                lo = xb[(size_t)(2 * c2) * NN + n];
                hi = xb[(size_t)(2 * c2 + 1) * NN + n];
            }
            s_x2[i] = pack_f16x2(lo, hi);
        }
    }
    // ---- stage coords tile (zero-padded) ----
    {
        const float* cb = coords + (size_t)bt * 3 * NN;
        for (int i = tid; i < SC_ELEMS; i += NTHREADS) {
            int c = i / XS;
            int m = i - c * XS;
            int n = n_base + m - PADD;
            s_c[i] = (n >= 0 && n < NN) ? cb[c * NN + n] : 0.0f;
        }
    }
    __syncthreads();

    // ---- distance weights dw[k][j] = max(0, 1 - |dcoords| / sigma) ----
    for (int i = tid; i < KK * NT; i += NTHREADS) {
        int k = i / NT;
        int j = i - k * NT;
        float d0 = s_c[0 * XS + j + k] - s_c[0 * XS + j + PADD];
        float d1 = s_c[1 * XS + j + k] - s_c[1 * XS + j + PADD];
        float d2 = s_c[2 * XS + j + k] - s_c[2 * XS + j + PADD];
        float dd = d0 * d0 + d1 * d1 + d2 * d2;
        float w  = 1.0f - sqrtf(dd) * inv_sigma;
        s_dw[i]  = w > 0.0f ? w : 0.0f;
    }
    __syncthreads();

    // ---- warp GEMM: 32 n (2 m16) x 64 f (8 n8); dw applied post-MMA per tap ----
    const int n0 = wid * 32 + gid;               // A/D base row

    float acc[2][8][4];
    #pragma unroll
    for (int mt = 0; mt < 2; ++mt)
        #pragma unroll
        for (int ft = 0; ft < 8; ++ft)
            #pragma unroll
            for (int r = 0; r < 4; ++r) acc[mt][ft][r] = 0.0f;

    const float fzero = 0.0f;

    #pragma unroll 1
    for (int k = 0; k < KK; ++k) {
        // dw at this thread's 4 row positions (f32, applied post-MMA)
        const float dwv0 = s_dw[k * NT + n0];
        const float dwv1 = s_dw[k * NT + n0 + 8];
        const float dwv2 = s_dw[k * NT + n0 + 16];
        const float dwv3 = s_dw[k * NT + n0 + 24];

        // A words: pure f16x2 x pairs. c2 rows: h*8 + tig (lo k8) / +4 (hi k8);
        // n rows: n0+k + {0,8,16,24}. All conflict-free.
        const unsigned* xr = s_x2 + n0 + k;
        unsigned al[2][4], ah[2][4];
        #pragma unroll
        for (int h = 0; h < 2; ++h) {
            const unsigned* plo = xr + (size_t)(h * 8 + tig) * XS;
            const unsigned* phi = xr + (size_t)(h * 8 + tig + 4) * XS;
            #pragma unroll
            for (int r = 0; r < 4; ++r) {
                al[h][r] = plo[r * 8];
                ah[h][r] = phi[r * 8];
            }
        }

        #pragma unroll
        for (int ft = 0; ft < 8; ++ft) {
            const uint2 b0 = s_wb2[((k * 2 + 0) * 8 + ft) * 32 + lane];   // h=0
            const uint2 b1 = s_wb2[((k * 2 + 1) * 8 + ft) * 32 + lane];   // h=1

            #pragma unroll
            for (int mt = 0; mt < 2; ++mt) {
                float tf[4];
                MMA_F16_INIT(tf, al[0][2*mt], al[0][2*mt+1], ah[0][2*mt], ah[0][2*mt+1],
                             b0.x, b0.y, fzero);
                MMA_F16_ACC (tf, al[1][2*mt], al[1][2*mt+1], ah[1][2*mt], ah[1][2*mt+1],
                             b1.x, b1.y);
                const float dlo = mt ? dwv2 : dwv0;
                const float dhi = mt ? dwv3 : dwv1;
                acc[mt][ft][0] = fmaf(dlo, tf[0], acc[mt][ft][0]);
                acc[mt][ft][1] = fmaf(dlo, tf[1], acc[mt][ft][1]);
                acc[mt][ft][2] = fmaf(dhi, tf[2], acc[mt][ft][2]);
                acc[mt][ft][3] = fmaf(dhi, tf[3], acc[mt][ft][3]);
            }
        }
    }

    // ---- epilogue: D row = n (gid/gid+8), col = f (2*tig, 2*tig+1) ----
    float* obase = out + (size_t)bt * FF * NN + n_base + n0;
    #pragma unroll
    for (int mt = 0; mt < 2; ++mt) {
        #pragma unroll
        for (int ft = 0; ft < 8; ++ft) {
            int f0 = ft * 8 + 2 * tig;
            float* p = obase + mt * 16 + (size_t)f0 * NN;
            p[0]      = acc[mt][ft][0];   // (n,   f0)
            p[NN]     = acc[mt][ft][1];   // (n,   f0+1)
            p[8]      = acc[mt][ft][2];   // (n+8, f0)
            p[NN + 8] = acc[mt][ft][3];   // (n+8, f0+1)
        }
    }
}

extern "C" void kernel_launch(void* const* d_in, const int* in_sizes, int n_in,
                              void* d_out, int out_size)
{
    const float* x      = (const float*)d_in[0];
    const float* coords = (const float*)d_in[1];
    const float* weight = (const float*)d_in[2];
    const void*  sig    = d_in[3];
    float*       out    = (float*)d_out;

    cudaFuncSetAttribute(swconv1d_mma16b_kernel,
                         cudaFuncAttributeMaxDynamicSharedMemorySize, SMEM_BYTES);

    dim3 grid(NN / NT, BB * TT);   // (64, 16)
    swconv1d_mma16b_kernel<<<grid, NTHREADS, SMEM_BYTES>>>(x, coords, weight, sig, out);
}